// round 10
// baseline (speedup 1.0000x reference)
#include <cuda_runtime.h>
#include <cuda_fp16.h>
#include <cstdint>

// ---------------------------------------------------------------------------
// Problem constants
// ---------------------------------------------------------------------------
#define M_TOK   64
#define KDIM    8192
#define NOUT    14336
#define KW      (KDIM / 2)          // 4096 int32 per output row
#define NTILE   128
#define GRID_N  (NOUT / NTILE)      // 112 CTAs = one wave

// SMEM: weight ring 6 x 16KB (one half-chunk = 64 k x 128 rows each),
//       x ring 4 x 16KB (one iteration = 128 k each). Total 160KB.
#define WSTAGES 6
#define WSTAGE  16384
#define XOFF    (WSTAGES * WSTAGE)  // 98304
#define XSTAGE  16384
#define SMEM_TOTAL (XOFF + 4 * XSTAGE)  // 163840

// x (fp16, k-permuted + bank-swizzled) staged per 64-k chunk: 128 chunks x 8KB
__device__ __align__(16) unsigned char g_ximg[(size_t)M_TOK * KDIM * 2];  // 1 MB

// ---------------------------------------------------------------------------
// Helpers
// ---------------------------------------------------------------------------
__device__ __forceinline__ void cp16(uint32_t saddr, const void* g) {
    asm volatile("cp.async.cg.shared.global [%0], [%1], 16;" :: "r"(saddr), "l"(g));
}
__device__ __forceinline__ void cp_commit() {
    asm volatile("cp.async.commit_group;" ::: "memory");
}
__device__ __forceinline__ uint2 lds64(uint32_t addr) {
    uint2 r;
    asm volatile("ld.shared.v2.u32 {%0,%1}, [%2];" : "=r"(r.x), "=r"(r.y) : "r"(addr));
    return r;
}
__device__ __forceinline__ uint4 lds128(uint32_t addr) {
    uint4 r;
    asm volatile("ld.shared.v4.u32 {%0,%1,%2,%3}, [%4];"
                 : "=r"(r.x), "=r"(r.y), "=r"(r.z), "=r"(r.w) : "r"(addr));
    return r;
}
__device__ __forceinline__ void mma16816(float* d, uint32_t a0, uint32_t a1,
                                         uint32_t a2, uint32_t a3,
                                         uint32_t b0, uint32_t b1) {
    asm volatile(
        "mma.sync.aligned.m16n8k16.row.col.f32.f16.f16.f32 "
        "{%0,%1,%2,%3}, {%4,%5,%6,%7}, {%8,%9}, {%0,%1,%2,%3};"
        : "+f"(d[0]), "+f"(d[1]), "+f"(d[2]), "+f"(d[3])
        : "r"(a0), "r"(a1), "r"(a2), "r"(a3), "r"(b0), "r"(b1));
}

// int4-pair dequant: one int32 (value 0..255; lo nibble = even k) -> f16x2 {qlo,qhi}.
// lo half = 0x6408 ^ nibLo = 1032 + qlo (exact); HSUB2 by 1032 -> exact signed int4.
__device__ __forceinline__ uint32_t dq2(uint32_t v) {
    uint32_t t = (v & 0xFu) ^ 0x64086408u;
    uint32_t p = t ^ ((v << 12) & 0x000F0000u);
    __half2 hp = *reinterpret_cast<__half2*>(&p);
    __half2 r = __hsub2(hp, __half2half2(__ushort_as_half((unsigned short)0x6408)));
    return *reinterpret_cast<uint32_t*>(&r);
}

// ---------------------------------------------------------------------------
// Pre-kernel: x [64,8192] f32 -> f16 with the k-permutation + LDS swizzle baked in.
// Chunk cc covers physical k [cc*64, cc*64+64). Granule q (q = 4c+s, c=q>>2, s=q&3)
// stores 4 halves = physical k {8c+2s, 8c+2s+1, 32+8c+2s, 33+8c+2s} at byte offset
// tok*128 + ((q ^ (tok&7)) * 8) inside the 8KB chunk tile.
// ---------------------------------------------------------------------------
__global__ void convert_x(const float* __restrict__ x) {
    int tg  = blockIdx.x * 256 + threadIdx.x;    // 131072 threads
    int cc  = tg >> 10;
    int rem = tg & 1023;
    int tok = rem >> 4;
    int q   = rem & 15;
    int c = q >> 2, s = q & 3;
    int k0 = cc * 64 + 8 * c + 2 * s;
    float2 v0 = *reinterpret_cast<const float2*>(x + (size_t)tok * KDIM + k0);
    float2 v1 = *reinterpret_cast<const float2*>(x + (size_t)tok * KDIM + k0 + 32);
    __half2 h0 = __floats2half2_rn(v0.x, v0.y);
    __half2 h1 = __floats2half2_rn(v1.x, v1.y);
    uint2 st;
    st.x = *reinterpret_cast<uint32_t*>(&h0);
    st.y = *reinterpret_cast<uint32_t*>(&h1);
    *reinterpret_cast<uint2*>(g_ximg + (size_t)cc * 8192 + tok * 128 +
                              ((q ^ (tok & 7)) << 3)) = st;
}

// ---------------------------------------------------------------------------
// Main kernel: CTA = 128 out-rows x 64 tokens, 256 threads / 8 warps in an
// 8(row) x 1(token) grid; warp tile = 16 rows x 64 tokens. K loop over 128
// half-chunks (64 k each). Weights flow through a 6-stage cp.async SMEM ring
// (distance 5, wait_group 4 -> 64KB in flight/SM, breaking the register-MLP
// ceiling that capped R8 at 2.6TB/s); x through a 4-stage cp.async ring.
//
// Weight stage layout: row r (0..127) at r*128; 16B granule g (int32s 4g..4g+3
// of the half-chunk) stored at (g ^ sw(r))*16, sw(r)=((r&1)<<2)|((r>>1)&3).
// sw is a bijection on 0..7 -> STS phases (8 rows, same g) conflict-free;
// sw(2k)^sw(2k+1)=4 -> LDS.128 phases (rows rl,rl+1 x cl 0..3) conflict-free.
// All swizzle XORs are applied to pure byte OFFSETS; sb is added last.
// ---------------------------------------------------------------------------
__global__ __launch_bounds__(256, 1)
void qmain(const int* __restrict__ wp, const float* __restrict__ ws,
           const float* __restrict__ bias, float* __restrict__ out) {
    extern __shared__ __align__(16) unsigned char smem[];

    const int tid  = threadIdx.x;
    const int lane = tid & 31, wr = tid >> 5;         // wr 0..7 = row-warp
    const int rl = lane >> 2, cl = lane & 3;
    const int r0 = blockIdx.x * NTILE;

    const uint32_t sb = (uint32_t)__cvta_generic_to_shared(smem);

    // ---- weight STS side: thread covers row (tid&127), granules gb..gb+3 ----
    const int srow = tid & 127;
    const int sgb  = (tid >> 7) * 4;
    const uint32_t swr = ((uint32_t)(srow & 1) << 2) | (((uint32_t)srow >> 1) & 3);
    const int* wsrc = wp + (size_t)(r0 + srow) * KW;   // + h*32 + (sgb+i)*4
    uint32_t wdst[4];                                   // offsets within a stage
#pragma unroll
    for (int i = 0; i < 4; i++)
        wdst[i] = (uint32_t)srow * 128 + ((((uint32_t)(sgb + i)) ^ swr) << 4);

    // ---- weight LDS side: rows wr*16 + rh*8 + rl; granules cl and cl^4 ----
    const uint32_t swl = ((uint32_t)(rl & 1) << 2) | (((uint32_t)rl >> 1) & 3);
    uint32_t wlo[2];                                    // offsets within a stage
#pragma unroll
    for (int rh = 0; rh < 2; rh++)
        wlo[rh] = (uint32_t)(wr * 16 + rh * 8 + rl) * 128 +
                  (((uint32_t)cl ^ swl) << 4);

    // ---- x fragment offsets (within x region): token = nt*8 + rl ----
    uint32_t baddr[8];
#pragma unroll
    for (int nt = 0; nt < 8; nt++)
        baddr[nt] = sb + XOFF + (uint32_t)(nt * 8 + rl) * 128;
    uint32_t gq[4];
#pragma unroll
    for (int s = 0; s < 4; s++)
        gq[s] = (uint32_t)(((4 * cl + s) ^ rl) << 3);

#define ISSUE_W(h_, slot_) do {                                                 \
        if ((h_) < 128) {                                                       \
            const uint32_t so_ = sb + (uint32_t)(slot_) * WSTAGE;               \
            const int* ws_ = wsrc + (h_) * 32 + sgb * 4;                        \
            _Pragma("unroll")                                                   \
            for (int i_ = 0; i_ < 4; i_++)                                      \
                cp16(so_ + wdst[i_], ws_ + i_ * 4);                             \
        } } while (0)

#define ISSUE_X(it_, slot_) do {                                               \
        const unsigned char* xg_ = g_ximg + (size_t)(it_) * 16384 + tid * 64;  \
        const uint32_t xd_ = sb + XOFF + (uint32_t)(slot_) * XSTAGE +          \
                             (uint32_t)tid * 64;                               \
        cp16(xd_,      xg_);      cp16(xd_ + 16, xg_ + 16);                    \
        cp16(xd_ + 32, xg_ + 32); cp16(xd_ + 48, xg_ + 48);                    \
    } while (0)

#define COMP4(u4, s_) ((s_) == 0 ? (u4).x : (s_) == 1 ? (u4).y : (s_) == 2 ? (u4).z : (u4).w)

// sx_ is an offset RELATIVE to the x region (0..57344); baddr already has sb+XOFF.
#define COMPUTE(W, sx_) do {                                                    \
        _Pragma("unroll")                                                       \
        for (int s_ = 0; s_ < 4; s_++) {                                        \
            uint32_t a0 = dq2(COMP4(W[0][0], s_));                              \
            uint32_t a1 = dq2(COMP4(W[1][0], s_));                              \
            uint32_t a2 = dq2(COMP4(W[0][1], s_));                              \
            uint32_t a3 = dq2(COMP4(W[1][1], s_));                              \
            _Pragma("unroll")                                                   \
            for (int nt_ = 0; nt_ < 8; nt_++) {                                 \
                uint2 b_ = lds64(baddr[nt_] + (sx_) + gq[s_]);                  \
                mma16816(d[nt_], a0, a1, a2, a3, b_.x, b_.y);                   \
            }                                                                   \
        } } while (0)

    float d[8][4] = {};

    // Prologue: weight halves 0..4 + x iterations 0..2 in flight (5 groups)
    ISSUE_W(0, 0); ISSUE_X(0, 0); cp_commit();
    ISSUE_W(1, 1); ISSUE_X(1, 1); cp_commit();
    ISSUE_W(2, 2); ISSUE_X(2, 2); cp_commit();
    ISSUE_W(3, 3); cp_commit();
    ISSUE_W(4, 4); cp_commit();

    int scur = 0;   // slot of half h
    int s5   = 5;   // slot of half h+5
    for (int h = 0; h < 128; h++) {
        asm volatile("cp.async.wait_group 4;" ::: "memory");
        __syncthreads();   // visibility of other threads' cp.async fills

        // Load this half's weight fragments from SMEM (conflict-free LDS.128)
        uint4 W[2][2];
        {
            const uint32_t so = sb + (uint32_t)scur * WSTAGE;
#pragma unroll
            for (int rh = 0; rh < 2; rh++) {
                W[rh][0] = lds128(so + wlo[rh]);
                W[rh][1] = lds128(so + (wlo[rh] ^ 64u));  // XOR on offset only
            }
        }
        const uint32_t sx = (uint32_t)((h >> 1) & 3) * XSTAGE +
                            (uint32_t)(h & 1) * 8192u;
        COMPUTE(W, sx);

        // Refill: W(h+5) into slot (h-1)%6 (its readers finished before the
        // barrier above); x(j+3) at even halves into slot (j+3)&3.
        ISSUE_W(h + 5, s5);
        if (!(h & 1)) {
            const int jn = (h >> 1) + 3;
            if (jn < 64) ISSUE_X(jn, jn & 3);
        }
        cp_commit();   // one group per half: uniform numbering for wait_group 4

        if (++scur == WSTAGES) scur = 0;
        if (++s5 == WSTAGES) s5 = 0;
    }

    // Epilogue: scale + bias. d[nt][0,1] = row rl, tokens 2cl,2cl+1;
    // d[nt][2,3] = row rl+8. STG lanes rl-consecutive -> full 32B sectors.
    const int R0g = r0 + wr * 16 + rl;
    const float sc0 = ws[R0g],     bi0 = bias[R0g];
    const float sc1 = ws[R0g + 8], bi1 = bias[R0g + 8];
#pragma unroll
    for (int nt = 0; nt < 8; nt++) {
        const int T = nt * 8 + 2 * cl;
        out[(size_t)T * NOUT + R0g]           = d[nt][0] * sc0 + bi0;
        out[(size_t)(T + 1) * NOUT + R0g]     = d[nt][1] * sc0 + bi0;
        out[(size_t)T * NOUT + R0g + 8]       = d[nt][2] * sc1 + bi1;
        out[(size_t)(T + 1) * NOUT + R0g + 8] = d[nt][3] * sc1 + bi1;
    }
}

// ---------------------------------------------------------------------------
extern "C" void kernel_launch(void* const* d_in, const int* in_sizes, int n_in,
                              void* d_out, int out_size) {
    (void)in_sizes; (void)n_in; (void)out_size;
    const float* x    = (const float*)d_in[0];
    const int*   wpk  = (const int*)d_in[1];
    const float* wsc  = (const float*)d_in[2];
    const float* bias = (const float*)d_in[3];
    float* out = (float*)d_out;

    cudaFuncSetAttribute(qmain, cudaFuncAttributeMaxDynamicSharedMemorySize, SMEM_TOTAL);
    convert_x<<<512, 256>>>(x);                               // 131072 threads
    qmain<<<GRID_N, 256, SMEM_TOTAL>>>(wpk, wsc, bias, out);  // 112 CTAs, one wave
}